// round 11
// baseline (speedup 1.0000x reference)
#include <cuda_runtime.h>
#include <cuda_bf16.h>
#include <math.h>

// DWT1D Haar analysis via banded-matrix exploit (2 taps/row, periodic).
// out[b,k,c]   = h00*x[b,2k,c] + h01*x[b,2k+1,c]   (same linear offset as x[b,2k,c])
// out[b,k,C+c] = h10*x[b,2k,c] + h11*x[b,2k+1,c]   (same linear offset as x[b,2k+1,c])
//
// Round-11: champion R9 body (streaming loads+stores, 10.688us best) with
// the final untested knob value: TPB 512 (halves CTA count; occ unchanged at
// 2048 thr/SM). TPB=128 regressed, so probing the other direction closes the
// axis. Op is at the mixed read/write HBM roofline: 67MB irreducible traffic
// @ ~6.27TB/s combined (78% of 8TB/s spec) — the physical ceiling for a
// 50/50 interleaved read/write stream.

__global__ void __launch_bounds__(512) dwt1d_haar_r11(
    const float4* __restrict__ x,
    const float*  __restrict__ A,
    float4*       __restrict__ out,
    int n_threads,            // total float4-pair slots = total_floats/8
    size_t half_row_off)      // (N/2)*N
{
    int idx = blockIdx.x * blockDim.x + threadIdx.x;
    if (idx >= n_threads) return;

    const float h00 = __ldg(&A[0]);
    const float h01 = __ldg(&A[1]);
    const float h10 = __ldg(&A[half_row_off]);
    const float h11 = __ldg(&A[half_row_off + 1]);

    // slot -> (pair, c): even-row float4 at pair*32 + c, odd-row at +16.
    const int pair = idx >> 4;
    const int c    = idx & 15;
    const size_t base = (size_t)pair * 32 + c;

    const float4 a = __ldcs(&x[base]);        // x[b, 2k,   4c:4c+4] (streaming)
    const float4 b = __ldcs(&x[base + 16]);   // x[b, 2k+1, 4c:4c+4] (streaming)

    float4 lo, hi;
    lo.x = a.x * h00 + b.x * h01;
    lo.y = a.y * h00 + b.y * h01;
    lo.z = a.z * h00 + b.z * h01;
    lo.w = a.w * h00 + b.w * h01;

    hi.x = a.x * h10 + b.x * h11;
    hi.y = a.y * h10 + b.y * h11;
    hi.z = a.z * h10 + b.z * h11;
    hi.w = a.w * h10 + b.w * h11;

    __stcs(&out[base],      lo);   // lowpass  band (streaming store)
    __stcs(&out[base + 16], hi);   // highpass band (streaming store)
}

extern "C" void kernel_launch(void* const* d_in, const int* in_sizes, int n_in,
                              void* d_out, int out_size)
{
    const float* x = (const float*)d_in[0];   // [B, N, C] f32
    const float* A = (const float*)d_in[1];   // [N, N]    f32
    float* out = (float*)d_out;               // [B, N/2, 2C] f32

    long long a_elems = (long long)in_sizes[1];
    int N = (int)llround(sqrt((double)a_elems));
    size_t half_row_off = (size_t)(N / 2) * (size_t)N;

    long long total = (long long)in_sizes[0];
    int n_threads = (int)(total / 8);         // 8 floats per thread

    const int TPB = 512;
    int blocks = (n_threads + TPB - 1) / TPB;

    dwt1d_haar_r11<<<blocks, TPB>>>(
        (const float4*)x, A, (float4*)out, n_threads, half_row_off);
}

// round 12
// speedup vs baseline: 1.0029x; 1.0029x over previous
#include <cuda_runtime.h>
#include <cuda_bf16.h>
#include <math.h>

// DWT1D Haar analysis via banded-matrix exploit (2 taps/row, periodic).
//
// The reference einsum('nm,bmc->bnc', A, x) uses a 4096x4096 analysis matrix
// with only 2 nonzeros per row (Haar filter bank, stride-2, periodic). The
// dense GEMM (275 GFLOP + 64MB of A) reduces to a pure streaming elementwise
// op with a linear-offset identity:
//   out[b,k,c]   = h00*x[b,2k,c] + h01*x[b,2k+1,c]  (same linear offset as x[b,2k,c])
//   out[b,k,C+c] = h10*x[b,2k,c] + h11*x[b,2k+1,c]  (same linear offset as x[b,2k+1,c])
// Taps read from A itself (A[0,0], A[0,1], A[N/2,0], A[N/2,1]) so any 2-tap
// periodic filter bank stays correct.
//
// FINAL (champion of 11 rounds): TPB=256, float4, streaming loads+stores.
// 10.688us = 67MB irreducible traffic @ ~6.27TB/s combined (78% of 8TB/s
// HBM spec) — the mixed read/write stream roofline. All structural axes
// (MLP 2-8, occupancy 37-80%, LDG.128/.256, persistent vs multi-wave grid,
// every L2 cache-policy combination, TPB 128/256/512) measured neutral or
// worse across rounds 1-11.

__global__ void __launch_bounds__(256) dwt1d_haar_final(
    const float4* __restrict__ x,
    const float*  __restrict__ A,
    float4*       __restrict__ out,
    int n_threads,            // total float4-pair slots = total_floats/8
    size_t half_row_off)      // (N/2)*N
{
    int idx = blockIdx.x * blockDim.x + threadIdx.x;
    if (idx >= n_threads) return;

    const float h00 = __ldg(&A[0]);
    const float h01 = __ldg(&A[1]);
    const float h10 = __ldg(&A[half_row_off]);
    const float h11 = __ldg(&A[half_row_off + 1]);

    // slot -> (pair, c): even-row float4 at pair*32 + c, odd-row at +16.
    const int pair = idx >> 4;
    const int c    = idx & 15;
    const size_t base = (size_t)pair * 32 + c;

    const float4 a = __ldcs(&x[base]);        // x[b, 2k,   4c:4c+4] (streaming)
    const float4 b = __ldcs(&x[base + 16]);   // x[b, 2k+1, 4c:4c+4] (streaming)

    float4 lo, hi;
    lo.x = a.x * h00 + b.x * h01;
    lo.y = a.y * h00 + b.y * h01;
    lo.z = a.z * h00 + b.z * h01;
    lo.w = a.w * h00 + b.w * h01;

    hi.x = a.x * h10 + b.x * h11;
    hi.y = a.y * h10 + b.y * h11;
    hi.z = a.z * h10 + b.z * h11;
    hi.w = a.w * h10 + b.w * h11;

    __stcs(&out[base],      lo);   // lowpass  band (streaming store)
    __stcs(&out[base + 16], hi);   // highpass band (streaming store)
}

extern "C" void kernel_launch(void* const* d_in, const int* in_sizes, int n_in,
                              void* d_out, int out_size)
{
    const float* x = (const float*)d_in[0];   // [B, N, C] f32
    const float* A = (const float*)d_in[1];   // [N, N]    f32
    float* out = (float*)d_out;               // [B, N/2, 2C] f32

    long long a_elems = (long long)in_sizes[1];
    int N = (int)llround(sqrt((double)a_elems));
    size_t half_row_off = (size_t)(N / 2) * (size_t)N;

    long long total = (long long)in_sizes[0];
    int n_threads = (int)(total / 8);         // 8 floats per thread

    const int TPB = 256;
    int blocks = (n_threads + TPB - 1) / TPB;

    dwt1d_haar_final<<<blocks, TPB>>>(
        (const float4*)x, A, (float4*)out, n_threads, half_row_off);
}

// round 13
// speedup vs baseline: 1.0239x; 1.0209x over previous
#include <cuda_runtime.h>
#include <cuda_bf16.h>
#include <math.h>

// DWT1D Haar analysis via banded-matrix exploit (2 taps/row, periodic).
// out[b,k,c]   = h00*x[b,2k,c] + h01*x[b,2k+1,c]  (same linear offset as x[b,2k,c])
// out[b,k,C+c] = h10*x[b,2k,c] + h11*x[b,2k+1,c]  (same linear offset as x[b,2k+1,c])
// Taps read from A (A[0,0], A[0,1], A[N/2,0], A[N/2,1]).
//
// Round-13: last untested store mode — __stwt (write-through). Write stream
// bypasses L2 allocation entirely; reads keep streaming (.cs). Closes the
// {wb, cs, wt} store-path sweep. Op is pinned at the mixed read/write HBM
// roofline (67MB @ ~6.2TB/s = 78% of spec); run-to-run noise calibrated at
// +/-0.25us, which brackets all 11 prior variants.

__global__ void __launch_bounds__(256) dwt1d_haar_r13(
    const float4* __restrict__ x,
    const float*  __restrict__ A,
    float4*       __restrict__ out,
    int n_threads,            // total float4-pair slots = total_floats/8
    size_t half_row_off)      // (N/2)*N
{
    int idx = blockIdx.x * blockDim.x + threadIdx.x;
    if (idx >= n_threads) return;

    const float h00 = __ldg(&A[0]);
    const float h01 = __ldg(&A[1]);
    const float h10 = __ldg(&A[half_row_off]);
    const float h11 = __ldg(&A[half_row_off + 1]);

    // slot -> (pair, c): even-row float4 at pair*32 + c, odd-row at +16.
    const int pair = idx >> 4;
    const int c    = idx & 15;
    const size_t base = (size_t)pair * 32 + c;

    const float4 a = __ldcs(&x[base]);        // x[b, 2k,   4c:4c+4] (streaming)
    const float4 b = __ldcs(&x[base + 16]);   // x[b, 2k+1, 4c:4c+4] (streaming)

    float4 lo, hi;
    lo.x = a.x * h00 + b.x * h01;
    lo.y = a.y * h00 + b.y * h01;
    lo.z = a.z * h00 + b.z * h01;
    lo.w = a.w * h00 + b.w * h01;

    hi.x = a.x * h10 + b.x * h11;
    hi.y = a.y * h10 + b.y * h11;
    hi.z = a.z * h10 + b.z * h11;
    hi.w = a.w * h10 + b.w * h11;

    __stwt(&out[base],      lo);   // lowpass  band (write-through)
    __stwt(&out[base + 16], hi);   // highpass band (write-through)
}

extern "C" void kernel_launch(void* const* d_in, const int* in_sizes, int n_in,
                              void* d_out, int out_size)
{
    const float* x = (const float*)d_in[0];   // [B, N, C] f32
    const float* A = (const float*)d_in[1];   // [N, N]    f32
    float* out = (float*)d_out;               // [B, N/2, 2C] f32

    long long a_elems = (long long)in_sizes[1];
    int N = (int)llround(sqrt((double)a_elems));
    size_t half_row_off = (size_t)(N / 2) * (size_t)N;

    long long total = (long long)in_sizes[0];
    int n_threads = (int)(total / 8);         // 8 floats per thread

    const int TPB = 256;
    int blocks = (n_threads + TPB - 1) / TPB;

    dwt1d_haar_r13<<<blocks, TPB>>>(
        (const float4*)x, A, (float4*)out, n_threads, half_row_off);
}